// round 1
// baseline (speedup 1.0000x reference)
#include <cuda_runtime.h>
#include <cuda_bf16.h>
#include <math.h>

// Problem constants
static constexpr int NB = 4096;   // batch
static constexpr int NL = 16;     // seq length
static constexpr int NH = 256;    // hidden
static constexpr int NLAT = 64;   // latent
static constexpr int NV = 800;    // vocab
static constexpr int STEPS = NL - 1;  // 15

// ---------------- device scratch (allocation-free) ----------------
__device__ float g_mfwd[STEPS * NB * NH];   // m_fwd[t][b][h]
__device__ float g_mrev[STEPS * NB * NH];   // m_rev[t][b][h] (indexed by t after reversal)
__device__ float g_rm[NB * NH];             // GRU carry r*m
__device__ float g_WzT[2 * NH * NH];        // [512][256]
__device__ float g_WhT[2 * NH * NH];        // [512][256]
__device__ float g_CT [2 * NH * NH];        // [Wr^T ; Ur^T]  [512][256]
__device__ float g_WqT[(NH + NLAT) * NH];   // [320][256]
__device__ float g_UpT[(2 * NH + NLAT) * NH]; // [576][256]
__device__ float g_WoT[NH * NV];            // [256][800]
__device__ double g_qloss, g_ploss;
__device__ unsigned long long g_qcnt, g_pcnt;

// ---------------- init ----------------
__global__ void k_init() {
    if (threadIdx.x == 0) {
        g_qloss = 0.0; g_ploss = 0.0; g_qcnt = 0ULL; g_pcnt = 0ULL;
    }
}

// ---------------- weight transpose:  dst[c*R + r] = src[r*C + c] ----------------
__global__ void k_transpose(const float* __restrict__ src, int R, int C, int which) {
    float* dst;
    switch (which) {
        case 0: dst = g_WzT; break;
        case 1: dst = g_WhT; break;
        case 2: dst = g_CT; break;               // Wr part
        case 3: dst = g_CT + NH * NH; break;     // Ur part
        case 4: dst = g_WqT; break;
        case 5: dst = g_UpT; break;
        default: dst = g_WoT; break;
    }
    int idx = blockIdx.x * blockDim.x + threadIdx.x;
    if (idx < R * C) {
        int r = idx / C, c = idx % C;
        dst[c * R + r] = src[idx];
    }
}

// ---------------- one GRU step (fused 3 GEMMs + gates) ----------------
// mode 0: fwd step t:  src=x[t], dst=x[t+1], m_prev=m_fwd[t-1], out=m_fwd[t]
// mode 1: rev step k:  src=x[15-k], dst=x[14-k], m_prev=m_rev[15-k], out=m_rev[14-k]
__global__ __launch_bounds__(256) void k_gru(const int* __restrict__ wid,
                                             const float* __restrict__ emb,
                                             const float* __restrict__ bz,
                                             const float* __restrict__ bh,
                                             const float* __restrict__ br,
                                             int mode, int step) {
    __shared__ float sx[16][NH];
    __shared__ float sm[16][NH];
    __shared__ float sr[16][NH];
    const int j = threadIdx.x;
    const int row0 = blockIdx.x * 16;

    int ts, td;
    const float* m_prev;
    float* m_out;
    if (mode == 0) {
        ts = step; td = step + 1;
        m_prev = (step == 0) ? nullptr : &g_mfwd[(step - 1) * NB * NH];
        m_out = &g_mfwd[step * NB * NH];
    } else {
        ts = 15 - step; td = 14 - step;
        m_prev = (step == 0) ? nullptr : &g_mrev[(15 - step) * NB * NH];
        m_out = &g_mrev[(14 - step) * NB * NH];
    }

    #pragma unroll
    for (int r = 0; r < 16; r++) {
        int b = row0 + r;
        int w = wid[b * NL + ts];
        sx[r][j] = emb[w * NH + j];
        if (m_prev) { sm[r][j] = m_prev[b * NH + j]; sr[r][j] = g_rm[b * NH + j]; }
        else        { sm[r][j] = 0.f;                sr[r][j] = 0.f; }
    }
    __syncthreads();

    float accZ[16], accH[16];
    #pragma unroll
    for (int r = 0; r < 16; r++) { accZ[r] = 0.f; accH[r] = 0.f; }

    // K part 1: x_src feeds both z and h_til
    for (int k = 0; k < NH; k += 4) {
        float wz0 = g_WzT[(k + 0) * NH + j], wz1 = g_WzT[(k + 1) * NH + j];
        float wz2 = g_WzT[(k + 2) * NH + j], wz3 = g_WzT[(k + 3) * NH + j];
        float wh0 = g_WhT[(k + 0) * NH + j], wh1 = g_WhT[(k + 1) * NH + j];
        float wh2 = g_WhT[(k + 2) * NH + j], wh3 = g_WhT[(k + 3) * NH + j];
        #pragma unroll
        for (int r = 0; r < 16; r++) {
            float4 a = *(const float4*)&sx[r][k];
            accZ[r] = fmaf(a.x, wz0, accZ[r]);
            accZ[r] = fmaf(a.y, wz1, accZ[r]);
            accZ[r] = fmaf(a.z, wz2, accZ[r]);
            accZ[r] = fmaf(a.w, wz3, accZ[r]);
            accH[r] = fmaf(a.x, wh0, accH[r]);
            accH[r] = fmaf(a.y, wh1, accH[r]);
            accH[r] = fmaf(a.z, wh2, accH[r]);
            accH[r] = fmaf(a.w, wh3, accH[r]);
        }
    }
    // K part 2: m_prev -> z, rm_prev -> h_til
    for (int k = 0; k < NH; k += 4) {
        float wz0 = g_WzT[(NH + k + 0) * NH + j], wz1 = g_WzT[(NH + k + 1) * NH + j];
        float wz2 = g_WzT[(NH + k + 2) * NH + j], wz3 = g_WzT[(NH + k + 3) * NH + j];
        float wh0 = g_WhT[(NH + k + 0) * NH + j], wh1 = g_WhT[(NH + k + 1) * NH + j];
        float wh2 = g_WhT[(NH + k + 2) * NH + j], wh3 = g_WhT[(NH + k + 3) * NH + j];
        #pragma unroll
        for (int r = 0; r < 16; r++) {
            float4 am = *(const float4*)&sm[r][k];
            float4 ar = *(const float4*)&sr[r][k];
            accZ[r] = fmaf(am.x, wz0, accZ[r]);
            accZ[r] = fmaf(am.y, wz1, accZ[r]);
            accZ[r] = fmaf(am.z, wz2, accZ[r]);
            accZ[r] = fmaf(am.w, wz3, accZ[r]);
            accH[r] = fmaf(ar.x, wh0, accH[r]);
            accH[r] = fmaf(ar.y, wh1, accH[r]);
            accH[r] = fmaf(ar.z, wh2, accH[r]);
            accH[r] = fmaf(ar.w, wh3, accH[r]);
        }
    }

    // gates + m
    const float bzv = bz[j], bhv = bh[j];
    #pragma unroll
    for (int r = 0; r < 16; r++) {
        float z = 1.f / (1.f + expf(-(accZ[r] + bzv)));
        float h = tanhf(accH[r] + bhv);
        float mp = sm[r][j];
        float m = (1.f - z) * mp + z * h;
        accZ[r] = m;  // stash
        m_out[(row0 + r) * NH + j] = m;
    }
    __syncthreads();

    // restage: sx <- x_dst (gather), sr <- m
    #pragma unroll
    for (int r = 0; r < 16; r++) {
        int b = row0 + r;
        int w = wid[b * NL + td];
        sx[r][j] = emb[w * NH + j];
        sr[r][j] = accZ[r];
    }
    __syncthreads();

    float accR[16];
    #pragma unroll
    for (int r = 0; r < 16; r++) accR[r] = 0.f;
    for (int k = 0; k < NH; k += 4) {
        float wr0 = g_CT[(k + 0) * NH + j], wr1 = g_CT[(k + 1) * NH + j];
        float wr2 = g_CT[(k + 2) * NH + j], wr3 = g_CT[(k + 3) * NH + j];
        float ur0 = g_CT[(NH + k + 0) * NH + j], ur1 = g_CT[(NH + k + 1) * NH + j];
        float ur2 = g_CT[(NH + k + 2) * NH + j], ur3 = g_CT[(NH + k + 3) * NH + j];
        #pragma unroll
        for (int r = 0; r < 16; r++) {
            float4 ax = *(const float4*)&sx[r][k];
            float4 am = *(const float4*)&sr[r][k];
            accR[r] = fmaf(ax.x, wr0, accR[r]);
            accR[r] = fmaf(ax.y, wr1, accR[r]);
            accR[r] = fmaf(ax.z, wr2, accR[r]);
            accR[r] = fmaf(ax.w, wr3, accR[r]);
            accR[r] = fmaf(am.x, ur0, accR[r]);
            accR[r] = fmaf(am.y, ur1, accR[r]);
            accR[r] = fmaf(am.z, ur2, accR[r]);
            accR[r] = fmaf(am.w, ur3, accR[r]);
        }
    }
    const float brv = br[j];
    #pragma unroll
    for (int r = 0; r < 16; r++) {
        float rg = 1.f / (1.f + expf(-(accR[r] + brv)));
        g_rm[(row0 + r) * NH + j] = rg * sr[r][j];
    }
}

// ---------------- q path: hidden GEMM + logits GEMM + fused logsumexp/argmax/loss ----------------
__global__ __launch_bounds__(256) void k_q(const int* __restrict__ wid,
                                           const float* __restrict__ tree,
                                           const float* __restrict__ Wb,
                                           const float* __restrict__ Wob) {
    extern __shared__ float smem[];
    float* hid = smem;                 // 16 x 256
    float* buf = smem + 16 * NH;       // 16 x 800 (input reuses first 16x320)
    __shared__ float s_red[16];
    __shared__ int s_cnt[16];
    const int j = threadIdx.x;
    const int row0 = blockIdx.x * 16;
    const int t = row0 / NB;           // 4096 % 16 == 0 -> constant per block

    // assemble q_in rows [m_fwd[t-1][b] | tree_vec[b]]
    for (int r = 0; r < 16; r++) {
        int b = row0 + r - t * NB;
        for (int k = j; k < NH + NLAT; k += 256) {
            float v;
            if (k < NH) v = (t == 0) ? 0.f : g_mfwd[(t - 1) * NB * NH + b * NH + k];
            else        v = tree[b * NLAT + (k - NH)];
            buf[r * 320 + k] = v;
        }
    }
    __syncthreads();

    // hidden = relu(q_in @ W_w^T + b)
    float acc[16];
    #pragma unroll
    for (int r = 0; r < 16; r++) acc[r] = 0.f;
    for (int k = 0; k < 320; k += 4) {
        float w0 = g_WqT[(k + 0) * NH + j], w1 = g_WqT[(k + 1) * NH + j];
        float w2 = g_WqT[(k + 2) * NH + j], w3 = g_WqT[(k + 3) * NH + j];
        #pragma unroll
        for (int r = 0; r < 16; r++) {
            float4 a = *(const float4*)&buf[r * 320 + k];
            acc[r] = fmaf(a.x, w0, acc[r]);
            acc[r] = fmaf(a.y, w1, acc[r]);
            acc[r] = fmaf(a.z, w2, acc[r]);
            acc[r] = fmaf(a.w, w3, acc[r]);
        }
    }
    const float wbv = Wb[j];
    #pragma unroll
    for (int r = 0; r < 16; r++) hid[r * NH + j] = fmaxf(acc[r] + wbv, 0.f);
    __syncthreads();

    // logits into smem buf[16][800]
    for (int g = 0; g < 4; g++) {
        int c = g * 256 + j;
        if (c < NV) {
            float accq[16];
            #pragma unroll
            for (int r = 0; r < 16; r++) accq[r] = 0.f;
            for (int k = 0; k < NH; k += 4) {
                float w0 = g_WoT[(k + 0) * NV + c], w1 = g_WoT[(k + 1) * NV + c];
                float w2 = g_WoT[(k + 2) * NV + c], w3 = g_WoT[(k + 3) * NV + c];
                #pragma unroll
                for (int r = 0; r < 16; r++) {
                    float4 h4 = *(const float4*)&hid[r * NH + k];
                    accq[r] = fmaf(h4.x, w0, accq[r]);
                    accq[r] = fmaf(h4.y, w1, accq[r]);
                    accq[r] = fmaf(h4.z, w2, accq[r]);
                    accq[r] = fmaf(h4.w, w3, accq[r]);
                }
            }
            float wob = Wob[c];
            #pragma unroll
            for (int r = 0; r < 16; r++) buf[r * NV + c] = accq[r] + wob;
        }
    }
    __syncthreads();

    // per-row: logsumexp, select, argmax (first-occurrence ties)
    const int warp = j >> 5, lane = j & 31;
    for (int rr = 0; rr < 2; rr++) {
        int r = warp + rr * 8;
        float mx = -1e30f; int ai = 0;
        for (int c = lane; c < NV; c += 32) {
            float v = buf[r * NV + c];
            if (v > mx) { mx = v; ai = c; }
        }
        for (int off = 16; off; off >>= 1) {
            float vo = __shfl_xor_sync(0xffffffffu, mx, off);
            int io = __shfl_xor_sync(0xffffffffu, ai, off);
            if (vo > mx || (vo == mx && io < ai)) { mx = vo; ai = io; }
        }
        float sum = 0.f;
        for (int c = lane; c < NV; c += 32) sum += expf(buf[r * NV + c] - mx);
        for (int off = 16; off; off >>= 1) sum += __shfl_xor_sync(0xffffffffu, sum, off);
        if (lane == 0) {
            int b = row0 + r - t * NB;
            int qt = wid[b * NL + t];
            float logZ = mx + logf(sum);
            s_red[r] = logZ - buf[r * NV + qt];
            s_cnt[r] = (ai == qt) ? 1 : 0;
        }
    }
    __syncthreads();
    if (j == 0) {
        double sum = 0.0; unsigned long long c = 0;
        for (int r = 0; r < 16; r++) { sum += (double)s_red[r]; c += (unsigned long long)s_cnt[r]; }
        atomicAdd(&g_qloss, sum);
        atomicAdd(&g_qcnt, c);
    }
}

// ---------------- p path: hidden GEMM + dot + fused loss ----------------
__global__ __launch_bounds__(256) void k_p(const int* __restrict__ wid,
                                           const float* __restrict__ tree,
                                           const float* __restrict__ emb,
                                           const float* __restrict__ Ub,
                                           const float* __restrict__ Usw,
                                           const float* __restrict__ Usb) {
    extern __shared__ float smem[];
    float* a = smem;                 // 16 x 576
    float* hid = smem + 16 * 576;    // 16 x 256
    __shared__ float s_red[16];
    __shared__ int s_cnt[16];
    const int j = threadIdx.x;
    const int row0 = blockIdx.x * 16;
    const int s = row0 / NB;
    const int tx = (s == 0) ? 0 : (s <= 15 ? s : 30 - s);

    for (int r = 0; r < 16; r++) {
        int b = row0 + r - s * NB;
        int w = wid[b * NL + tx];
        for (int k = j; k < 576; k += 256) {
            float v;
            if (k < 256) v = emb[w * NH + k];
            else if (k < 512) {
                int kk = k - 256;
                if (s == 0) v = 0.f;
                else if (s <= 15) v = g_mfwd[(s - 1) * NB * NH + b * NH + kk];
                else {
                    int jj = 30 - s;
                    v = g_mrev[jj * NB * NH + b * NH + kk];
                    if (jj > 0) v += g_mfwd[(jj - 1) * NB * NH + b * NH + kk];
                }
            } else v = tree[b * NLAT + (k - 512)];
            a[r * 576 + k] = v;
        }
    }
    __syncthreads();

    float acc[16];
    #pragma unroll
    for (int r = 0; r < 16; r++) acc[r] = 0.f;
    for (int k = 0; k < 576; k += 4) {
        float w0 = g_UpT[(k + 0) * NH + j], w1 = g_UpT[(k + 1) * NH + j];
        float w2 = g_UpT[(k + 2) * NH + j], w3 = g_UpT[(k + 3) * NH + j];
        #pragma unroll
        for (int r = 0; r < 16; r++) {
            float4 a4 = *(const float4*)&a[r * 576 + k];
            acc[r] = fmaf(a4.x, w0, acc[r]);
            acc[r] = fmaf(a4.y, w1, acc[r]);
            acc[r] = fmaf(a4.z, w2, acc[r]);
            acc[r] = fmaf(a4.w, w3, acc[r]);
        }
    }
    const float ubv = Ub[j];
    #pragma unroll
    for (int r = 0; r < 16; r++) hid[r * NH + j] = fmaxf(acc[r] + ubv, 0.f);
    __syncthreads();

    const int warp = j >> 5, lane = j & 31;
    const float ptv = (s < 15) ? 1.f : 0.f;
    for (int rr = 0; rr < 2; rr++) {
        int r = warp + rr * 8;
        float ps = 0.f;
        for (int c = lane; c < NH; c += 32) ps += hid[r * NH + c] * Usw[c];
        for (int off = 16; off; off >>= 1) ps += __shfl_xor_sync(0xffffffffu, ps, off);
        if (lane == 0) {
            float p = ps + Usb[0];
            float loss = fmaxf(p, 0.f) + log1pf(expf(-fabsf(p))) - p * ptv;
            s_red[r] = loss;
            s_cnt[r] = ((p > 0.f) == (ptv > 0.5f)) ? 1 : 0;
        }
    }
    __syncthreads();
    if (j == 0) {
        double sum = 0.0; unsigned long long c = 0;
        for (int r = 0; r < 16; r++) { sum += (double)s_red[r]; c += (unsigned long long)s_cnt[r]; }
        atomicAdd(&g_ploss, sum);
        atomicAdd(&g_pcnt, c);
    }
}

// ---------------- finalize ----------------
__global__ void k_fin(float* __restrict__ out) {
    out[0] = (float)(g_qloss / (double)NB);
    out[1] = (float)(g_ploss / (double)NB);
    out[2] = (float)((double)g_qcnt / (double)(NL * NB));
    out[3] = (float)((double)g_pcnt / (double)((2 * NL - 1) * NB));
}

extern "C" void kernel_launch(void* const* d_in, const int* in_sizes, int n_in,
                              void* d_out, int out_size) {
    const int*   wid  = (const int*)  d_in[0];
    const float* tree = (const float*)d_in[1];
    const float* emb  = (const float*)d_in[2];
    const float* Wz_w = (const float*)d_in[3];
    const float* Wz_b = (const float*)d_in[4];
    const float* Wr_w = (const float*)d_in[5];
    const float* Ur_w = (const float*)d_in[6];
    const float* Ur_b = (const float*)d_in[7];
    const float* Wh_w = (const float*)d_in[8];
    const float* Wh_b = (const float*)d_in[9];
    const float* W_w  = (const float*)d_in[10];
    const float* W_b  = (const float*)d_in[11];
    const float* U_w  = (const float*)d_in[12];
    const float* U_b  = (const float*)d_in[13];
    const float* Wo_w = (const float*)d_in[14];
    const float* Wo_b = (const float*)d_in[15];
    const float* Us_w = (const float*)d_in[16];
    const float* Us_b = (const float*)d_in[17];
    float* out = (float*)d_out;

    const int q_smem = (16 * NH + 16 * NV) * 4;        // 67584 B
    const int p_smem = (16 * 576 + 16 * NH) * 4;       // 53248 B
    cudaFuncSetAttribute(k_q, cudaFuncAttributeMaxDynamicSharedMemorySize, q_smem);
    cudaFuncSetAttribute(k_p, cudaFuncAttributeMaxDynamicSharedMemorySize, p_smem);

    k_init<<<1, 32>>>();

    auto tg = [](int n) { return (n + 255) / 256; };
    k_transpose<<<tg(256 * 512), 256>>>(Wz_w, 256, 512, 0);
    k_transpose<<<tg(256 * 512), 256>>>(Wh_w, 256, 512, 1);
    k_transpose<<<tg(256 * 256), 256>>>(Wr_w, 256, 256, 2);
    k_transpose<<<tg(256 * 256), 256>>>(Ur_w, 256, 256, 3);
    k_transpose<<<tg(256 * 320), 256>>>(W_w,  256, 320, 4);
    k_transpose<<<tg(256 * 576), 256>>>(U_w,  256, 576, 5);
    k_transpose<<<tg(800 * 256), 256>>>(Wo_w, 800, 256, 6);

    for (int t = 0; t < STEPS; t++)
        k_gru<<<NB / 16, 256>>>(wid, emb, Wz_b, Wh_b, Ur_b, 0, t);
    for (int t = 0; t < STEPS; t++)
        k_gru<<<NB / 16, 256>>>(wid, emb, Wz_b, Wh_b, Ur_b, 1, t);

    k_q<<<(NL * NB) / 16, 256, q_smem>>>(wid, tree, W_b, Wo_b);
    k_p<<<((2 * NL - 1) * NB) / 16, 256, p_smem>>>(wid, tree, emb, U_b, Us_w, Us_b);
    k_fin<<<1, 1>>>(out);
}

// round 5
// speedup vs baseline: 1.6167x; 1.6167x over previous
#include <cuda_runtime.h>
#include <cuda_bf16.h>
#include <math.h>

// Problem constants
static constexpr int NB = 4096;   // batch
static constexpr int NL = 16;     // seq length
static constexpr int NH = 256;    // hidden
static constexpr int NLAT = 64;   // latent
static constexpr int NV = 800;    // vocab
static constexpr int STEPS = NL - 1;  // 15

// ---------------- packed f32x2 helpers ----------------
#define FFMA2(acc, a, b) asm("fma.rn.f32x2 %0, %1, %2, %0;" : "+l"(acc) : "l"(a), "l"(b))

static __device__ __forceinline__ float2 unpack2(unsigned long long v) {
    float2 f;
    asm("mov.b64 {%0, %1}, %2;" : "=f"(f.x), "=f"(f.y) : "l"(v));
    return f;
}

// ---------------- device scratch (allocation-free) ----------------
__device__ float g_mfwd[STEPS * NB * NH];
__device__ float g_mrev[STEPS * NB * NH];
__device__ float g_rm[NB * NH];
// pair-interleaved weights: float index ((k>>2)*J + col)*4 + (k&3), stored as ulonglong2 (16B aligned)
__device__ ulonglong2 g_Wz4[512 * 256 / 4];
__device__ ulonglong2 g_Wh4[512 * 256 / 4];
__device__ ulonglong2 g_C4 [512 * 256 / 4];   // [Wr ; Ur]
__device__ ulonglong2 g_Wq4[320 * 256 / 4];
__device__ ulonglong2 g_Up4[576 * 256 / 4];
__device__ ulonglong2 g_Wo4[256 * 800 / 4];
__device__ double g_qloss, g_ploss;
__device__ unsigned long long g_qcnt, g_pcnt;

// ---------------- init ----------------
__global__ void k_init() {
    if (threadIdx.x == 0) {
        g_qloss = 0.0; g_ploss = 0.0; g_qcnt = 0ULL; g_pcnt = 0ULL;
    }
}

// ---------------- repack: src[J][K] row-major -> dst interleaved ----------------
__global__ void k_repack(const float* __restrict__ src, int J, int K, int which, int koff) {
    float* dst;
    switch (which) {
        case 0: dst = (float*)g_Wz4; break;
        case 1: dst = (float*)g_Wh4; break;
        case 2: dst = (float*)g_C4;  break;
        case 3: dst = (float*)g_Wq4; break;
        case 4: dst = (float*)g_Up4; break;
        default: dst = (float*)g_Wo4; break;
    }
    int idx = blockIdx.x * blockDim.x + threadIdx.x;
    if (idx < J * K) {
        int jcol = idx / K, k = idx % K;
        int kk = k + koff;
        dst[((kk >> 2) * J + jcol) * 4 + (kk & 3)] = src[jcol * K + k];
    }
}

// ---------------- one GRU step (fused 3 GEMMs + gates), FFMA2 ----------------
__global__ __launch_bounds__(256, 2) void k_gru(const int* __restrict__ wid,
                                                const float* __restrict__ emb,
                                                const float* __restrict__ bz,
                                                const float* __restrict__ bh,
                                                const float* __restrict__ br,
                                                int mode, int step) {
    __shared__ __align__(16) float sx[16][NH];
    __shared__ __align__(16) float sm[16][NH];
    __shared__ __align__(16) float sr[16][NH];
    const int j = threadIdx.x;
    const int row0 = blockIdx.x * 16;

    int ts, td;
    const float* m_prev;
    float* m_out;
    if (mode == 0) {
        ts = step; td = step + 1;
        m_prev = (step == 0) ? nullptr : &g_mfwd[(step - 1) * NB * NH];
        m_out = &g_mfwd[step * NB * NH];
    } else {
        ts = 15 - step; td = 14 - step;
        m_prev = (step == 0) ? nullptr : &g_mrev[(15 - step) * NB * NH];
        m_out = &g_mrev[(14 - step) * NB * NH];
    }

    #pragma unroll
    for (int r = 0; r < 16; r++) {
        int b = row0 + r;
        int w = wid[b * NL + ts];
        sx[r][j] = emb[w * NH + j];
        if (m_prev) { sm[r][j] = m_prev[b * NH + j]; sr[r][j] = g_rm[b * NH + j]; }
        else        { sm[r][j] = 0.f;                sr[r][j] = 0.f; }
    }
    __syncthreads();

    const ulonglong2* SX = (const ulonglong2*)sx;   // [r*64 + kk]
    const ulonglong2* SM = (const ulonglong2*)sm;
    const ulonglong2* SR = (const ulonglong2*)sr;

    // ---- Z = sigmoid([x|m] @ WzT + bz) ----
    unsigned long long acc2[16];
    #pragma unroll
    for (int r = 0; r < 16; r++) acc2[r] = 0ULL;
    #pragma unroll 2
    for (int kk = 0; kk < 64; kk++) {
        ulonglong2 w = g_Wz4[kk * NH + j];
        #pragma unroll
        for (int r = 0; r < 16; r++) {
            ulonglong2 a = SX[r * 64 + kk];
            FFMA2(acc2[r], a.x, w.x);
            FFMA2(acc2[r], a.y, w.y);
        }
    }
    #pragma unroll 2
    for (int kk = 0; kk < 64; kk++) {
        ulonglong2 w = g_Wz4[(64 + kk) * NH + j];
        #pragma unroll
        for (int r = 0; r < 16; r++) {
            ulonglong2 a = SM[r * 64 + kk];
            FFMA2(acc2[r], a.x, w.x);
            FFMA2(acc2[r], a.y, w.y);
        }
    }
    float zg[16];
    const float bzv = bz[j];
    #pragma unroll
    for (int r = 0; r < 16; r++) {
        float2 t = unpack2(acc2[r]);
        zg[r] = 1.f / (1.f + expf(-(t.x + t.y + bzv)));
    }

    // ---- H = tanh([x|rm] @ WhT + bh) ; m = (1-z)*m_prev + z*h ----
    #pragma unroll
    for (int r = 0; r < 16; r++) acc2[r] = 0ULL;
    #pragma unroll 2
    for (int kk = 0; kk < 64; kk++) {
        ulonglong2 w = g_Wh4[kk * NH + j];
        #pragma unroll
        for (int r = 0; r < 16; r++) {
            ulonglong2 a = SX[r * 64 + kk];
            FFMA2(acc2[r], a.x, w.x);
            FFMA2(acc2[r], a.y, w.y);
        }
    }
    #pragma unroll 2
    for (int kk = 0; kk < 64; kk++) {
        ulonglong2 w = g_Wh4[(64 + kk) * NH + j];
        #pragma unroll
        for (int r = 0; r < 16; r++) {
            ulonglong2 a = SR[r * 64 + kk];
            FFMA2(acc2[r], a.x, w.x);
            FFMA2(acc2[r], a.y, w.y);
        }
    }
    float marr[16];
    const float bhv = bh[j];
    #pragma unroll
    for (int r = 0; r < 16; r++) {
        float2 t = unpack2(acc2[r]);
        float h = tanhf(t.x + t.y + bhv);
        float m = (1.f - zg[r]) * sm[r][j] + zg[r] * h;
        marr[r] = m;
        m_out[(row0 + r) * NH + j] = m;
    }
    __syncthreads();

    // restage: sx <- x_dst, sr <- m
    #pragma unroll
    for (int r = 0; r < 16; r++) {
        int b = row0 + r;
        int w = wid[b * NL + td];
        sx[r][j] = emb[w * NH + j];
        sr[r][j] = marr[r];
    }
    __syncthreads();

    // ---- R = sigmoid(x_dst @ WrT + m @ UrT + br) ; rm = r*m ----
    #pragma unroll
    for (int r = 0; r < 16; r++) acc2[r] = 0ULL;
    #pragma unroll 2
    for (int kk = 0; kk < 64; kk++) {
        ulonglong2 w = g_C4[kk * NH + j];
        #pragma unroll
        for (int r = 0; r < 16; r++) {
            ulonglong2 a = SX[r * 64 + kk];
            FFMA2(acc2[r], a.x, w.x);
            FFMA2(acc2[r], a.y, w.y);
        }
    }
    #pragma unroll 2
    for (int kk = 0; kk < 64; kk++) {
        ulonglong2 w = g_C4[(64 + kk) * NH + j];
        #pragma unroll
        for (int r = 0; r < 16; r++) {
            ulonglong2 a = SR[r * 64 + kk];
            FFMA2(acc2[r], a.x, w.x);
            FFMA2(acc2[r], a.y, w.y);
        }
    }
    const float brv = br[j];
    #pragma unroll
    for (int r = 0; r < 16; r++) {
        float2 t = unpack2(acc2[r]);
        float rg = 1.f / (1.f + expf(-(t.x + t.y + brv)));
        g_rm[(row0 + r) * NH + j] = rg * marr[r];
    }
}

// ---------------- q path ----------------
__global__ __launch_bounds__(256, 2) void k_q(const int* __restrict__ wid,
                                              const float* __restrict__ tree,
                                              const float* __restrict__ Wb,
                                              const float* __restrict__ Wob) {
    extern __shared__ __align__(16) float smem[];
    float* hid = smem;                 // 16 x 256
    float* buf = smem + 16 * NH;       // 16 x 800 (input phase uses 16 x 320)
    __shared__ float s_red[16];
    __shared__ int s_cnt[16];
    const int j = threadIdx.x;
    const int row0 = blockIdx.x * 16;
    const int t = row0 / NB;

    for (int r = 0; r < 16; r++) {
        int b = row0 + r - t * NB;
        for (int k = j; k < NH + NLAT; k += 256) {
            float v;
            if (k < NH) v = (t == 0) ? 0.f : g_mfwd[(t - 1) * NB * NH + b * NH + k];
            else        v = tree[b * NLAT + (k - NH)];
            buf[r * 320 + k] = v;
        }
    }
    __syncthreads();

    const ulonglong2* BUF = (const ulonglong2*)buf;   // row stride 80
    unsigned long long acc2[16];
    #pragma unroll
    for (int r = 0; r < 16; r++) acc2[r] = 0ULL;
    #pragma unroll 2
    for (int kk = 0; kk < 80; kk++) {
        ulonglong2 w = g_Wq4[kk * NH + j];
        #pragma unroll
        for (int r = 0; r < 16; r++) {
            ulonglong2 a = BUF[r * 80 + kk];
            FFMA2(acc2[r], a.x, w.x);
            FFMA2(acc2[r], a.y, w.y);
        }
    }
    const float wbv = Wb[j];
    #pragma unroll
    for (int r = 0; r < 16; r++) {
        float2 tt = unpack2(acc2[r]);
        hid[r * NH + j] = fmaxf(tt.x + tt.y + wbv, 0.f);
    }
    __syncthreads();

    const ulonglong2* HID = (const ulonglong2*)hid;   // row stride 64
    for (int g = 0; g < 4; g++) {
        int c = g * 256 + j;
        if (c < NV) {
            unsigned long long aq[16];
            #pragma unroll
            for (int r = 0; r < 16; r++) aq[r] = 0ULL;
            #pragma unroll 2
            for (int kk = 0; kk < 64; kk++) {
                ulonglong2 w = g_Wo4[kk * NV + c];
                #pragma unroll
                for (int r = 0; r < 16; r++) {
                    ulonglong2 h = HID[r * 64 + kk];
                    FFMA2(aq[r], h.x, w.x);
                    FFMA2(aq[r], h.y, w.y);
                }
            }
            float wob = Wob[c];
            #pragma unroll
            for (int r = 0; r < 16; r++) {
                float2 tt = unpack2(aq[r]);
                buf[r * NV + c] = tt.x + tt.y + wob;
            }
        }
    }
    __syncthreads();

    const int warp = j >> 5, lane = j & 31;
    for (int rr = 0; rr < 2; rr++) {
        int r = warp + rr * 8;
        float mx = -1e30f; int ai = 0;
        for (int c = lane; c < NV; c += 32) {
            float v = buf[r * NV + c];
            if (v > mx) { mx = v; ai = c; }
        }
        for (int off = 16; off; off >>= 1) {
            float vo = __shfl_xor_sync(0xffffffffu, mx, off);
            int io = __shfl_xor_sync(0xffffffffu, ai, off);
            if (vo > mx || (vo == mx && io < ai)) { mx = vo; ai = io; }
        }
        float sum = 0.f;
        for (int c = lane; c < NV; c += 32) sum += expf(buf[r * NV + c] - mx);
        for (int off = 16; off; off >>= 1) sum += __shfl_xor_sync(0xffffffffu, sum, off);
        if (lane == 0) {
            int b = row0 + r - t * NB;
            int qt = wid[b * NL + t];
            float logZ = mx + logf(sum);
            s_red[r] = logZ - buf[r * NV + qt];
            s_cnt[r] = (ai == qt) ? 1 : 0;
        }
    }
    __syncthreads();
    if (j == 0) {
        double sum = 0.0; unsigned long long c = 0;
        for (int r = 0; r < 16; r++) { sum += (double)s_red[r]; c += (unsigned long long)s_cnt[r]; }
        atomicAdd(&g_qloss, sum);
        atomicAdd(&g_qcnt, c);
    }
}

// ---------------- p path ----------------
__global__ __launch_bounds__(256, 2) void k_p(const int* __restrict__ wid,
                                              const float* __restrict__ tree,
                                              const float* __restrict__ emb,
                                              const float* __restrict__ Ub,
                                              const float* __restrict__ Usw,
                                              const float* __restrict__ Usb) {
    extern __shared__ __align__(16) float smem[];
    float* a = smem;                 // 16 x 576
    float* hid = smem + 16 * 576;    // 16 x 256
    __shared__ float s_red[16];
    __shared__ int s_cnt[16];
    const int j = threadIdx.x;
    const int row0 = blockIdx.x * 16;
    const int s = row0 / NB;
    const int tx = (s == 0) ? 0 : (s <= 15 ? s : 30 - s);

    for (int r = 0; r < 16; r++) {
        int b = row0 + r - s * NB;
        int w = wid[b * NL + tx];
        for (int k = j; k < 576; k += 256) {
            float v;
            if (k < 256) v = emb[w * NH + k];
            else if (k < 512) {
                int kk = k - 256;
                if (s == 0) v = 0.f;
                else if (s <= 15) v = g_mfwd[(s - 1) * NB * NH + b * NH + kk];
                else {
                    int jj = 30 - s;
                    v = g_mrev[jj * NB * NH + b * NH + kk];
                    if (jj > 0) v += g_mfwd[(jj - 1) * NB * NH + b * NH + kk];
                }
            } else v = tree[b * NLAT + (k - 512)];
            a[r * 576 + k] = v;
        }
    }
    __syncthreads();

    const ulonglong2* A2 = (const ulonglong2*)a;   // row stride 144
    unsigned long long acc2[16];
    #pragma unroll
    for (int r = 0; r < 16; r++) acc2[r] = 0ULL;
    #pragma unroll 2
    for (int kk = 0; kk < 144; kk++) {
        ulonglong2 w = g_Up4[kk * NH + j];
        #pragma unroll
        for (int r = 0; r < 16; r++) {
            ulonglong2 av = A2[r * 144 + kk];
            FFMA2(acc2[r], av.x, w.x);
            FFMA2(acc2[r], av.y, w.y);
        }
    }
    const float ubv = Ub[j];
    #pragma unroll
    for (int r = 0; r < 16; r++) {
        float2 tt = unpack2(acc2[r]);
        hid[r * NH + j] = fmaxf(tt.x + tt.y + ubv, 0.f);
    }
    __syncthreads();

    const int warp = j >> 5, lane = j & 31;
    const float ptv = (s < 15) ? 1.f : 0.f;
    for (int rr = 0; rr < 2; rr++) {
        int r = warp + rr * 8;
        float ps = 0.f;
        for (int c = lane; c < NH; c += 32) ps += hid[r * NH + c] * Usw[c];
        for (int off = 16; off; off >>= 1) ps += __shfl_xor_sync(0xffffffffu, ps, off);
        if (lane == 0) {
            float p = ps + Usb[0];
            float loss = fmaxf(p, 0.f) + log1pf(expf(-fabsf(p))) - p * ptv;
            s_red[r] = loss;
            s_cnt[r] = ((p > 0.f) == (ptv > 0.5f)) ? 1 : 0;
        }
    }
    __syncthreads();
    if (j == 0) {
        double sum = 0.0; unsigned long long c = 0;
        for (int r = 0; r < 16; r++) { sum += (double)s_red[r]; c += (unsigned long long)s_cnt[r]; }
        atomicAdd(&g_ploss, sum);
        atomicAdd(&g_pcnt, c);
    }
}

// ---------------- finalize ----------------
__global__ void k_fin(float* __restrict__ out) {
    out[0] = (float)(g_qloss / (double)NB);
    out[1] = (float)(g_ploss / (double)NB);
    out[2] = (float)((double)g_qcnt / (double)(NL * NB));
    out[3] = (float)((double)g_pcnt / (double)((2 * NL - 1) * NB));
}

extern "C" void kernel_launch(void* const* d_in, const int* in_sizes, int n_in,
                              void* d_out, int out_size) {
    const int*   wid  = (const int*)  d_in[0];
    const float* tree = (const float*)d_in[1];
    const float* emb  = (const float*)d_in[2];
    const float* Wz_w = (const float*)d_in[3];
    const float* Wz_b = (const float*)d_in[4];
    const float* Wr_w = (const float*)d_in[5];
    const float* Ur_w = (const float*)d_in[6];
    const float* Ur_b = (const float*)d_in[7];
    const float* Wh_w = (const float*)d_in[8];
    const float* Wh_b = (const float*)d_in[9];
    const float* W_w  = (const float*)d_in[10];
    const float* W_b  = (const float*)d_in[11];
    const float* U_w  = (const float*)d_in[12];
    const float* U_b  = (const float*)d_in[13];
    const float* Wo_w = (const float*)d_in[14];
    const float* Wo_b = (const float*)d_in[15];
    const float* Us_w = (const float*)d_in[16];
    const float* Us_b = (const float*)d_in[17];
    float* out = (float*)d_out;

    const int q_smem = (16 * NH + 16 * NV) * 4;        // 67584 B
    const int p_smem = (16 * 576 + 16 * NH) * 4;       // 53248 B
    cudaFuncSetAttribute(k_q, cudaFuncAttributeMaxDynamicSharedMemorySize, q_smem);
    cudaFuncSetAttribute(k_p, cudaFuncAttributeMaxDynamicSharedMemorySize, p_smem);

    k_init<<<1, 32>>>();

    auto tg = [](int n) { return (n + 255) / 256; };
    k_repack<<<tg(256 * 512), 256>>>(Wz_w, 256, 512, 0, 0);
    k_repack<<<tg(256 * 512), 256>>>(Wh_w, 256, 512, 1, 0);
    k_repack<<<tg(256 * 256), 256>>>(Wr_w, 256, 256, 2, 0);
    k_repack<<<tg(256 * 256), 256>>>(Ur_w, 256, 256, 2, 256);
    k_repack<<<tg(256 * 320), 256>>>(W_w,  256, 320, 3, 0);
    k_repack<<<tg(256 * 576), 256>>>(U_w,  256, 576, 4, 0);
    k_repack<<<tg(800 * 256), 256>>>(Wo_w, 800, 256, 5, 0);

    for (int t = 0; t < STEPS; t++)
        k_gru<<<NB / 16, 256>>>(wid, emb, Wz_b, Wh_b, Ur_b, 0, t);
    for (int t = 0; t < STEPS; t++)
        k_gru<<<NB / 16, 256>>>(wid, emb, Wz_b, Wh_b, Ur_b, 1, t);

    k_q<<<(NL * NB) / 16, 256, q_smem>>>(wid, tree, W_b, Wo_b);
    k_p<<<((2 * NL - 1) * NB) / 16, 256, p_smem>>>(wid, tree, emb, U_b, Us_w, Us_b);
    k_fin<<<1, 1>>>(out);
}